// round 12
// baseline (speedup 1.0000x reference)
#include <cuda_runtime.h>
#include <cuda_bf16.h>
#include <cstdint>
#include <cstddef>

#define SEQ  3584
#define DIMN 2048
#define NHEAD 16
#define HD   128
#define MQ   3072

// ---------------------------------------------------------------------------
// Scratch (__device__ globals; alloc-free rule)
// ---------------------------------------------------------------------------
__device__ float g_q[SEQ * DIMN];
__device__ float g_k[SEQ * DIMN];
__device__ int   g_flash_ctr;

__device__ __nv_bfloat16 g_xh[SEQ * DIMN];
__device__ __nv_bfloat16 g_xl[SEQ * DIMN];
__device__ __nv_bfloat16 g_qh[SEQ * DIMN];
__device__ __nv_bfloat16 g_ql[SEQ * DIMN];
__device__ __nv_bfloat16 g_kh[SEQ * DIMN];
__device__ __nv_bfloat16 g_kl[SEQ * DIMN];
__device__ __nv_bfloat16 g_vh[SEQ * DIMN];
__device__ __nv_bfloat16 g_vl[SEQ * DIMN];
__device__ __nv_bfloat16 g_oh[SEQ * DIMN];
__device__ __nv_bfloat16 g_ol[SEQ * DIMN];
__device__ __nv_bfloat16 g_wqh[DIMN * DIMN];
__device__ __nv_bfloat16 g_wql[DIMN * DIMN];
__device__ __nv_bfloat16 g_wkh[DIMN * DIMN];
__device__ __nv_bfloat16 g_wkl[DIMN * DIMN];
__device__ __nv_bfloat16 g_wvh[DIMN * DIMN];
__device__ __nv_bfloat16 g_wvl[DIMN * DIMN];
__device__ __nv_bfloat16 g_woh[DIMN * DIMN];
__device__ __nv_bfloat16 g_wol[DIMN * DIMN];

// Single extern-shared symbol (shared by all kernels; cast locally)
extern __shared__ __align__(1024) char smem_dyn[];

// ---------------------------------------------------------------------------
// PTX helpers (baseline-PTX only; no tcgen05 on this build path)
// ---------------------------------------------------------------------------
__device__ __forceinline__ uint32_t smem_u32(const void* p) {
    uint32_t a;
    asm("{ .reg .u64 t; cvta.to.shared.u64 t, %1; cvt.u32.u64 %0, t; }"
        : "=r"(a) : "l"(p));
    return a;
}

__device__ __forceinline__ void cp16(uint32_t saddr, const void* gptr) {
    asm volatile("cp.async.cg.shared.global [%0], [%1], 16;" :: "r"(saddr), "l"(gptr));
}
#define CP_COMMIT() asm volatile("cp.async.commit_group;" ::: "memory")
#define CP_WAIT(n)  asm volatile("cp.async.wait_group %0;" :: "n"(n) : "memory")

__device__ __forceinline__ void ldm_x4(uint32_t (&r)[4], uint32_t addr) {
    asm volatile("ldmatrix.sync.aligned.m8n8.x4.shared.b16 {%0,%1,%2,%3}, [%4];"
        : "=r"(r[0]), "=r"(r[1]), "=r"(r[2]), "=r"(r[3]) : "r"(addr));
}
__device__ __forceinline__ void ldm_x4_t(uint32_t (&r)[4], uint32_t addr) {
    asm volatile("ldmatrix.sync.aligned.m8n8.x4.trans.shared.b16 {%0,%1,%2,%3}, [%4];"
        : "=r"(r[0]), "=r"(r[1]), "=r"(r[2]), "=r"(r[3]) : "r"(addr));
}

__device__ __forceinline__ void mma_bf16(float (&d)[4], const uint32_t (&a)[4],
                                         uint32_t b0, uint32_t b1) {
    asm volatile(
        "mma.sync.aligned.m16n8k16.row.col.f32.bf16.bf16.f32 "
        "{%0,%1,%2,%3}, {%4,%5,%6,%7}, {%8,%9}, {%0,%1,%2,%3};"
        : "+f"(d[0]), "+f"(d[1]), "+f"(d[2]), "+f"(d[3])
        : "r"(a[0]), "r"(a[1]), "r"(a[2]), "r"(a[3]), "r"(b0), "r"(b1));
}

__device__ __forceinline__ void splitpack(float a, float b, uint32_t& hi, uint32_t& lo) {
    __nv_bfloat16 ha = __float2bfloat16(a), hb = __float2bfloat16(b);
    __nv_bfloat16 la = __float2bfloat16(a - __bfloat162float(ha));
    __nv_bfloat16 lb = __float2bfloat16(b - __bfloat162float(hb));
    __nv_bfloat162 h2(ha, hb), l2(la, lb);
    hi = *(uint32_t*)&h2;
    lo = *(uint32_t*)&l2;
}

// ---------------------------------------------------------------------------
// fp32 -> bf16 hi/lo split (single + 4-way batched for weights)
// ---------------------------------------------------------------------------
__device__ __forceinline__ void cvt_body(const float* __restrict__ in,
                                         __nv_bfloat16* __restrict__ hi,
                                         __nv_bfloat16* __restrict__ lo, int i)
{
    float4 v = *(const float4*)&in[i];
    float f[4] = {v.x, v.y, v.z, v.w};
    __nv_bfloat16 h[4], l[4];
#pragma unroll
    for (int c = 0; c < 4; c++) {
        h[c] = __float2bfloat16(f[c]);
        l[c] = __float2bfloat16(f[c] - __bfloat162float(h[c]));
    }
    *(__nv_bfloat162*)&hi[i]     = __nv_bfloat162(h[0], h[1]);
    *(__nv_bfloat162*)&hi[i + 2] = __nv_bfloat162(h[2], h[3]);
    *(__nv_bfloat162*)&lo[i]     = __nv_bfloat162(l[0], l[1]);
    *(__nv_bfloat162*)&lo[i + 2] = __nv_bfloat162(l[2], l[3]);
}

__global__ void __launch_bounds__(256) cvt_hilo(const float* __restrict__ in,
                                                __nv_bfloat16* __restrict__ hi,
                                                __nv_bfloat16* __restrict__ lo,
                                                int n)
{
    int i = (blockIdx.x * 256 + threadIdx.x) * 4;
    if (i < n) cvt_body(in, hi, lo, i);
}

__global__ void __launch_bounds__(256) cvt_hilo4(
    const float* __restrict__ i0, __nv_bfloat16* h0, __nv_bfloat16* l0,
    const float* __restrict__ i1, __nv_bfloat16* h1, __nv_bfloat16* l1,
    const float* __restrict__ i2, __nv_bfloat16* h2, __nv_bfloat16* l2,
    const float* __restrict__ i3, __nv_bfloat16* h3, __nv_bfloat16* l3,
    int n)
{
    int i = (blockIdx.x * 256 + threadIdx.x) * 4;
    if (i >= n) return;
    const float* in = (blockIdx.y == 0) ? i0 : (blockIdx.y == 1) ? i1
                    : (blockIdx.y == 2) ? i2 : i3;
    __nv_bfloat16* hi = (blockIdx.y == 0) ? h0 : (blockIdx.y == 1) ? h1
                      : (blockIdx.y == 2) ? h2 : h3;
    __nv_bfloat16* lo = (blockIdx.y == 0) ? l0 : (blockIdx.y == 1) ? l1
                      : (blockIdx.y == 2) ? l2 : l3;
    cvt_body(in, hi, lo, i);
}

__global__ void reset_ctr() { g_flash_ctr = 0; }

// ---------------------------------------------------------------------------
// HMMA GEMM core (R9 config): CTA tile 128x128, BK=32, 256 threads = 8 warps
// (2m x 4n), warp tile 64x32, double-buffered cp.async, split-bf16 3-term.
// ---------------------------------------------------------------------------
#define GBK     32
#define GPITCH  40
#define TILE_E  (128 * GPITCH)
#define STAGE_E (4 * TILE_E)
#define GEMM_SMEM_BYTES (2 * STAGE_E * 2)   // 81920 -> 2 CTAs/SM

struct GemmOut {
    float* f;
    __nv_bfloat16* hi;
    __nv_bfloat16* lo;
};

__device__ __forceinline__ void gemm_body(
    const __nv_bfloat16* __restrict__ Ah, const __nv_bfloat16* __restrict__ Al,
    const __nv_bfloat16* __restrict__ Bh, const __nv_bfloat16* __restrict__ Bl,
    const float* __restrict__ bias, GemmOut out)
{
    __nv_bfloat16* sm = (__nv_bfloat16*)smem_dyn;
    const int tid  = threadIdx.x;
    const int lane = tid & 31;
    const int wid  = tid >> 5;
    const int m0 = blockIdx.y * 128;
    const int n0 = blockIdx.x * 128;
    const int wm0 = (wid & 1) * 64;
    const int wn0 = (wid >> 1) * 32;

    const __nv_bfloat16* srcs[4] = {Ah, Al, Bh, Bl};

    auto load_stage = [&](int stage, int it) {
        const int k0 = it * GBK;
        __nv_bfloat16* st = sm + stage * STAGE_E;
#pragma unroll
        for (int t = 0; t < 4; t++) {
            const __nv_bfloat16* src = srcs[t] + (size_t)(t < 2 ? m0 : n0) * DIMN + k0;
            __nv_bfloat16* tb = st + t * TILE_E;
#pragma unroll
            for (int i = 0; i < 2; i++) {
                int idx = tid + i * 256;
                int row = idx >> 2, ch = idx & 3;
                cp16(smem_u32(tb + row * GPITCH + ch * 8),
                     src + (size_t)row * DIMN + ch * 8);
            }
        }
    };

    float acc[4][4][4];
#pragma unroll
    for (int a = 0; a < 4; a++)
#pragma unroll
        for (int b = 0; b < 4; b++)
#pragma unroll
            for (int c = 0; c < 4; c++) acc[a][b][c] = 0.f;

    load_stage(0, 0);
    CP_COMMIT();

    const int arow = (lane & 7) + ((lane >> 3) & 1) * 8;
    const int acol = (lane >> 4) * 8;
    const int brow = (lane & 7) + (lane >> 4) * 8;
    const int bcol = ((lane >> 3) & 1) * 8;

    const int NIT = DIMN / GBK;
    for (int it = 0; it < NIT; it++) {
        const int b = it & 1;
        if (it + 1 < NIT) { load_stage(1 - b, it + 1); CP_COMMIT(); CP_WAIT(1); }
        else              { CP_WAIT(0); }
        __syncthreads();

        const __nv_bfloat16* sAh = sm + b * STAGE_E;
        const __nv_bfloat16* sAl = sAh + TILE_E;
        const __nv_bfloat16* sBh = sAh + 2 * TILE_E;
        const __nv_bfloat16* sBl = sAh + 3 * TILE_E;

#pragma unroll
        for (int ks = 0; ks < 2; ks++) {
            uint32_t fa[4][4], fbh[2][4], fbl[2][4];
#pragma unroll
            for (int mf = 0; mf < 4; mf++)
                ldm_x4(fa[mf], smem_u32(sAh + (wm0 + mf * 16 + arow) * GPITCH + ks * 16 + acol));
#pragma unroll
            for (int nf = 0; nf < 2; nf++)
                ldm_x4(fbh[nf], smem_u32(sBh + (wn0 + nf * 16 + brow) * GPITCH + ks * 16 + bcol));
#pragma unroll
            for (int mf = 0; mf < 4; mf++)
#pragma unroll
                for (int nf = 0; nf < 4; nf++)
                    mma_bf16(acc[mf][nf], fa[mf], fbh[nf >> 1][(nf & 1) * 2], fbh[nf >> 1][(nf & 1) * 2 + 1]);
#pragma unroll
            for (int nf = 0; nf < 2; nf++)
                ldm_x4(fbl[nf], smem_u32(sBl + (wn0 + nf * 16 + brow) * GPITCH + ks * 16 + bcol));
#pragma unroll
            for (int mf = 0; mf < 4; mf++)
#pragma unroll
                for (int nf = 0; nf < 4; nf++)
                    mma_bf16(acc[mf][nf], fa[mf], fbl[nf >> 1][(nf & 1) * 2], fbl[nf >> 1][(nf & 1) * 2 + 1]);
#pragma unroll
            for (int mf = 0; mf < 4; mf++)
                ldm_x4(fa[mf], smem_u32(sAl + (wm0 + mf * 16 + arow) * GPITCH + ks * 16 + acol));
#pragma unroll
            for (int mf = 0; mf < 4; mf++)
#pragma unroll
                for (int nf = 0; nf < 4; nf++)
                    mma_bf16(acc[mf][nf], fa[mf], fbh[nf >> 1][(nf & 1) * 2], fbh[nf >> 1][(nf & 1) * 2 + 1]);
        }
        __syncthreads();
    }

#pragma unroll
    for (int mf = 0; mf < 4; mf++) {
#pragma unroll
        for (int nf = 0; nf < 4; nf++) {
            int row = m0 + wm0 + mf * 16 + (lane >> 2);
            int col = n0 + wn0 + nf * 8 + (lane & 3) * 2;
            float b0 = bias[col], b1 = bias[col + 1];
            float f00 = acc[mf][nf][0] + b0, f01 = acc[mf][nf][1] + b1;
            float f10 = acc[mf][nf][2] + b0, f11 = acc[mf][nf][3] + b1;
            if (out.hi) {
                uint32_t h0, l0, h1, l1;
                splitpack(f00, f01, h0, l0);
                splitpack(f10, f11, h1, l1);
                *(uint32_t*)&out.hi[(size_t)row * DIMN + col]       = h0;
                *(uint32_t*)&out.lo[(size_t)row * DIMN + col]       = l0;
                *(uint32_t*)&out.hi[(size_t)(row + 8) * DIMN + col] = h1;
                *(uint32_t*)&out.lo[(size_t)(row + 8) * DIMN + col] = l1;
            } else {
                *(float2*)&out.f[(size_t)row * DIMN + col]       = make_float2(f00, f01);
                *(float2*)&out.f[(size_t)(row + 8) * DIMN + col] = make_float2(f10, f11);
            }
        }
    }
}

__global__ void __launch_bounds__(256) gemm_qkv(
    const __nv_bfloat16* __restrict__ xh, const __nv_bfloat16* __restrict__ xl,
    const __nv_bfloat16* __restrict__ wqh, const __nv_bfloat16* __restrict__ wql,
    const __nv_bfloat16* __restrict__ wkh, const __nv_bfloat16* __restrict__ wkl,
    const __nv_bfloat16* __restrict__ wvh, const __nv_bfloat16* __restrict__ wvl,
    const float* __restrict__ bq, const float* __restrict__ bk,
    const float* __restrict__ bv,
    float* outq, float* outk,
    __nv_bfloat16* vh_out, __nv_bfloat16* vl_out)
{
    const int z = blockIdx.z;
    const __nv_bfloat16* Bh = (z == 0) ? wqh : (z == 1) ? wkh : wvh;
    const __nv_bfloat16* Bl = (z == 0) ? wql : (z == 1) ? wkl : wvl;
    const float* bias = (z == 0) ? bq : (z == 1) ? bk : bv;
    GemmOut out;
    if (z == 2) { out.f = nullptr; out.hi = vh_out; out.lo = vl_out; }
    else        { out.f = z ? outk : outq; out.hi = nullptr; out.lo = nullptr; }
    gemm_body(xh, xl, Bh, Bl, bias, out);
}

__global__ void __launch_bounds__(256) gemm_out(
    const __nv_bfloat16* __restrict__ Ah, const __nv_bfloat16* __restrict__ Al,
    const __nv_bfloat16* __restrict__ Bh, const __nv_bfloat16* __restrict__ Bl,
    const float* __restrict__ bias, float* __restrict__ C)
{
    GemmOut out; out.f = C; out.hi = nullptr; out.lo = nullptr;
    gemm_body(Ah, Al, Bh, Bl, bias, out);
}

// ---------------------------------------------------------------------------
// RMSNorm + RoPE; reads fp32 q/k, writes bf16 hi/lo.
// q pre-scaled by log2(e)/sqrt(HD) so flash softmax uses exp2.
// ---------------------------------------------------------------------------
__global__ void __launch_bounds__(256) rms_rope(
    const float* __restrict__ qf, const float* __restrict__ kf,
    __nv_bfloat16* __restrict__ qh, __nv_bfloat16* __restrict__ ql,
    __nv_bfloat16* __restrict__ kh, __nv_bfloat16* __restrict__ kl,
    const float* __restrict__ gq, const float* __restrict__ gk,
    const float* __restrict__ freqs)
{
    const int row = blockIdx.x;
    const int which = blockIdx.y;
    const float* rowp = (which ? kf : qf) + (size_t)row * DIMN;
    __nv_bfloat16* oh = (which ? kh : qh) + (size_t)row * DIMN;
    __nv_bfloat16* ol = (which ? kl : ql) + (size_t)row * DIMN;
    const float* g = which ? gk : gq;
    const int tid = threadIdx.x;
    const float outscale = which ? 1.0f
        : (0.08838834764831845f * 1.4426950408889634f);   // log2(e)/sqrt(128)

    float ss = 0.f;
    for (int i = tid; i < DIMN; i += 256) { float v = rowp[i]; ss += v * v; }
#pragma unroll
    for (int o = 16; o > 0; o >>= 1) ss += __shfl_xor_sync(0xffffffffu, ss, o);

    __shared__ float wsum[8];
    __shared__ float sinvs;
    if ((tid & 31) == 0) wsum[tid >> 5] = ss;
    __syncthreads();
    if (tid == 0) {
        float t = 0.f;
#pragma unroll
        for (int i = 0; i < 8; i++) t += wsum[i];
        sinvs = rsqrtf(t * (1.0f / (float)DIMN) + 1e-6f);
    }
    __syncthreads();
    const float inv = sinvs;

    int f, h, w;
    if (row < MQ) { f = row >> 8; int rem = row & 255; h = rem >> 4; w = rem & 15; }
    else { int rr = row - MQ; f = 12 + (rr >> 8); int rem = rr & 255; h = rem >> 4; w = rem & 15; }

    for (int p = tid; p < DIMN / 2; p += 256) {
        int hp = p & 63;
        int pos = (hp < 22) ? f : ((hp < 43) ? h : w);
        float c = freqs[(pos * 64 + hp) * 2 + 0];
        float s = freqs[(pos * 64 + hp) * 2 + 1];
        float e = rowp[2 * p]     * inv * g[2 * p];
        float o = rowp[2 * p + 1] * inv * g[2 * p + 1];
        float r0 = (e * c - o * s) * outscale;
        float r1 = (e * s + o * c) * outscale;
        uint32_t hi, lo;
        splitpack(r0, r1, hi, lo);
        *(uint32_t*)&oh[2 * p] = hi;
        *(uint32_t*)&ol[2 * p] = lo;
    }
}

// ---------------------------------------------------------------------------
// Persistent HMMA flash attention. 148 CTAs x 256 threads pull (qtile, head)
// work items off a global atomic queue (long items first; shorts fill tail).
// Per item: Q tile 128 x 128, warp = 16 q-rows, K/V 64-row tiles
// double-buffered via cp.async; softmax (exp2) in registers; P in registers;
// bf16 hi/lo output. Item outputs disjoint -> deterministic.
// ---------------------------------------------------------------------------
#define FP2 136
#define FQH_B 0
#define FQL_B 34816
#define FSTG_B 69632
#define FSTG_SZ 69632
#define FKH_B 0
#define FKL_B 17408
#define FVH_B 34816
#define FVL_B 52224
#define FLASH3_SMEM (FSTG_B + 2 * FSTG_SZ)   // 208896
#define N_ITEMS 448   // 24*16 long + 4*16 short

__global__ void __launch_bounds__(256, 1) flash_hmma(
    const __nv_bfloat16* __restrict__ qh, const __nv_bfloat16* __restrict__ ql,
    const __nv_bfloat16* __restrict__ kh, const __nv_bfloat16* __restrict__ kl,
    const __nv_bfloat16* __restrict__ vh, const __nv_bfloat16* __restrict__ vl,
    __nv_bfloat16* __restrict__ ohp, __nv_bfloat16* __restrict__ olp)
{
    const uint32_t sb = smem_u32(smem_dyn);
    __shared__ int s_item;
    const int tid  = threadIdx.x;
    const int lane = tid & 31;
    const int wid  = tid >> 5;
    const int wrow = wid * 16;

    const int arow = (lane & 7) + ((lane >> 3) & 1) * 8;
    const int acol = (lane >> 4) * 8;
    const int brow = (lane & 7) + (lane >> 4) * 8;
    const int bcol = ((lane >> 3) & 1) * 8;

    while (true) {
        if (tid == 0) s_item = atomicAdd(&g_flash_ctr, 1);
        __syncthreads();
        const int item = s_item;
        if (item >= N_ITEMS) break;

        int qt, head;
        if (item < 384) { head = item / 24; qt = item % 24; }      // long: 56 k-tiles
        else { int j = item - 384; head = j / 4; qt = 24 + (j & 3); } // short: 4 k-tiles

        const int q0   = qt * 128;
        const int hoff = head * HD;

        // Q tiles (hi/lo)
        for (int i = tid; i < 128 * 16; i += 256) {
            int row = i >> 4, ch = i & 15;
            size_t goff = (size_t)(q0 + row) * DIMN + hoff + ch * 8;
            uint32_t soff = (uint32_t)(row * FP2 + ch * 8) * 2;
            cp16(sb + FQH_B + soff, qh + goff);
            cp16(sb + FQL_B + soff, ql + goff);
        }

        auto load_kv = [&](int stage, int kt) {
            const int k0 = kt * 64;
            const uint32_t stb = sb + FSTG_B + stage * FSTG_SZ;
            for (int i = tid; i < 64 * 16; i += 256) {
                int row = i >> 4, ch = i & 15;
                size_t goff = (size_t)(k0 + row) * DIMN + hoff + ch * 8;
                uint32_t soff = (uint32_t)(row * FP2 + ch * 8) * 2;
                cp16(stb + FKH_B + soff, kh + goff);
                cp16(stb + FKL_B + soff, kl + goff);
                cp16(stb + FVH_B + soff, vh + goff);
                cp16(stb + FVL_B + soff, vl + goff);
            }
        };

        int ktb, kte;
        if (qt < 24) { ktb = 0; kte = 56; }
        else { int j = (qt - 24) >> 1; ktb = 48 + j * 4; kte = ktb + 4; }
        const int nkt = kte - ktb;

        load_kv(0, ktb);
        CP_COMMIT();

        float o[16][4];
#pragma unroll
        for (int i = 0; i < 16; i++)
#pragma unroll
            for (int j = 0; j < 4; j++) o[i][j] = 0.f;
        float mrun0 = -1e30f, mrun1 = -1e30f;
        float lrun0 = 0.f, lrun1 = 0.f;

        for (int i = 0; i < nkt; i++) {
            if (i + 1 < nkt) { load_kv((i + 1) & 1, ktb + i + 1); CP_COMMIT(); CP_WAIT(1); }
            else             { CP_WAIT(0); }
            __syncthreads();
            const uint32_t stb = sb + FSTG_B + (i & 1) * FSTG_SZ;

            float s[8][4];
#pragma unroll
            for (int nf = 0; nf < 8; nf++)
#pragma unroll
                for (int c = 0; c < 4; c++) s[nf][c] = 0.f;

#pragma unroll
            for (int kc = 0; kc < 8; kc++) {
                uint32_t fqh_[4], fql_[4], fkh_[4][4], fkl_[4][4];
                uint32_t aoff = (uint32_t)((wrow + arow) * FP2 + kc * 16 + acol) * 2;
                ldm_x4(fqh_, sb + FQH_B + aoff);
                ldm_x4(fql_, sb + FQL_B + aoff);
#pragma unroll
                for (int b = 0; b < 4; b++) {
                    uint32_t boff = (uint32_t)((b * 16 + brow) * FP2 + kc * 16 + bcol) * 2;
                    ldm_x4(fkh_[b], stb + FKH_B + boff);
                    ldm_x4(fkl_[b], stb + FKL_B + boff);
                }
#pragma unroll
                for (int nf = 0; nf < 8; nf++) {
                    uint32_t bh0 = fkh_[nf >> 1][(nf & 1) * 2], bh1 = fkh_[nf >> 1][(nf & 1) * 2 + 1];
                    uint32_t bl0 = fkl_[nf >> 1][(nf & 1) * 2], bl1 = fkl_[nf >> 1][(nf & 1) * 2 + 1];
                    mma_bf16(s[nf], fqh_, bh0, bh1);
                    mma_bf16(s[nf], fqh_, bl0, bl1);
                    mma_bf16(s[nf], fql_, bh0, bh1);
                }
            }

            float mx0 = -1e30f, mx1 = -1e30f;
#pragma unroll
            for (int nf = 0; nf < 8; nf++) {
                mx0 = fmaxf(mx0, fmaxf(s[nf][0], s[nf][1]));
                mx1 = fmaxf(mx1, fmaxf(s[nf][2], s[nf][3]));
            }
            mx0 = fmaxf(mx0, __shfl_xor_sync(0xffffffffu, mx0, 1));
            mx0 = fmaxf(mx0, __shfl_xor_sync(0xffffffffu, mx0, 2));
            mx1 = fmaxf(mx1, __shfl_xor_sync(0xffffffffu, mx1, 1));
            mx1 = fmaxf(mx1, __shfl_xor_sync(0xffffffffu, mx1, 2));
            float m0 = fmaxf(mrun0, mx0), m1 = fmaxf(mrun1, mx1);
            float a0 = exp2f(mrun0 - m0), a1 = exp2f(mrun1 - m1);
            mrun0 = m0; mrun1 = m1;

            float sum0 = 0.f, sum1 = 0.f;
#pragma unroll
            for (int nf = 0; nf < 8; nf++) {
                s[nf][0] = exp2f(s[nf][0] - m0);
                s[nf][1] = exp2f(s[nf][1] - m0);
                s[nf][2] = exp2f(s[nf][2] - m1);
                s[nf][3] = exp2f(s[nf][3] - m1);
                sum0 += s[nf][0] + s[nf][1];
                sum1 += s[nf][2] + s[nf][3];
            }
            sum0 += __shfl_xor_sync(0xffffffffu, sum0, 1);
            sum0 += __shfl_xor_sync(0xffffffffu, sum0, 2);
            sum1 += __shfl_xor_sync(0xffffffffu, sum1, 1);
            sum1 += __shfl_xor_sync(0xffffffffu, sum1, 2);
            lrun0 = lrun0 * a0 + sum0;
            lrun1 = lrun1 * a1 + sum1;

#pragma unroll
            for (int nf = 0; nf < 16; nf++) {
                o[nf][0] *= a0; o[nf][1] *= a0;
                o[nf][2] *= a1; o[nf][3] *= a1;
            }

            uint32_t pha[4][4], pla[4][4];
#pragma unroll
            for (int c2 = 0; c2 < 4; c2++) {
                splitpack(s[2 * c2][0],     s[2 * c2][1],     pha[c2][0], pla[c2][0]);
                splitpack(s[2 * c2][2],     s[2 * c2][3],     pha[c2][1], pla[c2][1]);
                splitpack(s[2 * c2 + 1][0], s[2 * c2 + 1][1], pha[c2][2], pla[c2][2]);
                splitpack(s[2 * c2 + 1][2], s[2 * c2 + 1][3], pha[c2][3], pla[c2][3]);
            }

#pragma unroll
            for (int c2 = 0; c2 < 4; c2++) {
#pragma unroll
                for (int db = 0; db < 8; db++) {
                    uint32_t fvh_[4], fvl_[4];
                    uint32_t voff = (uint32_t)((c2 * 16 + arow) * FP2 + db * 16 + acol) * 2;
                    ldm_x4_t(fvh_, stb + FVH_B + voff);
                    ldm_x4_t(fvl_, stb + FVL_B + voff);
                    mma_bf16(o[2 * db],     pha[c2], fvh_[0], fvh_[1]);
                    mma_bf16(o[2 * db + 1], pha[c2], fvh_[2], fvh_[3]);
                    mma_bf16(o[2 * db],     pha[c2], fvl_[0], fvl_[1]);
                    mma_bf16(o[2 * db + 1], pha[c2], fvl_[2], fvl_[3]);
                    mma_bf16(o[2 * db],     pla[c2], fvh_[0], fvh_[1]);
                    mma_bf16(o[2 * db + 1], pla[c2], fvh_[2], fvh_[3]);
                }
            }
            __syncthreads();
        }

        // Epilogue: normalize, write bf16 hi/lo
        float inv0 = 1.0f / lrun0, inv1 = 1.0f / lrun1;
        int r0 = q0 + wrow + (lane >> 2);
        int r1 = r0 + 8;
        int cbase = hoff + (lane & 3) * 2;
#pragma unroll
        for (int nf = 0; nf < 16; nf++) {
            int col = cbase + nf * 8;
            float f0 = o[nf][0] * inv0, f1 = o[nf][1] * inv0;
            float f2 = o[nf][2] * inv1, f3 = o[nf][3] * inv1;
            uint32_t h01, l01, h23, l23;
            splitpack(f0, f1, h01, l01);
            splitpack(f2, f3, h23, l23);
            *(uint32_t*)&ohp[(size_t)r0 * DIMN + col] = h01;
            *(uint32_t*)&olp[(size_t)r0 * DIMN + col] = l01;
            *(uint32_t*)&ohp[(size_t)r1 * DIMN + col] = h23;
            *(uint32_t*)&olp[(size_t)r1 * DIMN + col] = l23;
        }
        __syncthreads();   // all warps done with smem before next item's loads
    }
}

// ---------------------------------------------------------------------------
// Launch
// ---------------------------------------------------------------------------
extern "C" void kernel_launch(void* const* d_in, const int* in_sizes, int n_in,
                              void* d_out, int out_size)
{
    (void)in_sizes; (void)n_in; (void)out_size;
    const float* x     = (const float*)d_in[0];
    const float* Wq    = (const float*)d_in[1];
    const float* bq    = (const float*)d_in[2];
    const float* Wk    = (const float*)d_in[3];
    const float* bk    = (const float*)d_in[4];
    const float* Wv    = (const float*)d_in[5];
    const float* bv    = (const float*)d_in[6];
    const float* Wo    = (const float*)d_in[7];
    const float* bo    = (const float*)d_in[8];
    const float* gq    = (const float*)d_in[9];
    const float* gk    = (const float*)d_in[10];
    const float* freqs = (const float*)d_in[11];
    float* out = (float*)d_out;

    float *pq, *pk;
    cudaGetSymbolAddress((void**)&pq, g_q);
    cudaGetSymbolAddress((void**)&pk, g_k);

    __nv_bfloat16 *xh, *xl, *oh, *ol;
    __nv_bfloat16 *qh, *ql, *kh, *kl, *vh, *vl;
    __nv_bfloat16 *wqh, *wql, *wkh, *wkl, *wvh, *wvl, *woh, *wol;
    cudaGetSymbolAddress((void**)&xh, g_xh);   cudaGetSymbolAddress((void**)&xl, g_xl);
    cudaGetSymbolAddress((void**)&oh, g_oh);   cudaGetSymbolAddress((void**)&ol, g_ol);
    cudaGetSymbolAddress((void**)&qh, g_qh);   cudaGetSymbolAddress((void**)&ql, g_ql);
    cudaGetSymbolAddress((void**)&kh, g_kh);   cudaGetSymbolAddress((void**)&kl, g_kl);
    cudaGetSymbolAddress((void**)&vh, g_vh);   cudaGetSymbolAddress((void**)&vl, g_vl);
    cudaGetSymbolAddress((void**)&wqh, g_wqh); cudaGetSymbolAddress((void**)&wql, g_wql);
    cudaGetSymbolAddress((void**)&wkh, g_wkh); cudaGetSymbolAddress((void**)&wkl, g_wkl);
    cudaGetSymbolAddress((void**)&wvh, g_wvh); cudaGetSymbolAddress((void**)&wvl, g_wvl);
    cudaGetSymbolAddress((void**)&woh, g_woh); cudaGetSymbolAddress((void**)&wol, g_wol);

    cudaFuncSetAttribute(gemm_qkv, cudaFuncAttributeMaxDynamicSharedMemorySize,
                         GEMM_SMEM_BYTES);
    cudaFuncSetAttribute(gemm_out, cudaFuncAttributeMaxDynamicSharedMemorySize,
                         GEMM_SMEM_BYTES);
    cudaFuncSetAttribute(flash_hmma, cudaFuncAttributeMaxDynamicSharedMemorySize,
                         FLASH3_SMEM);

    const int nx = SEQ * DIMN, nw = DIMN * DIMN;
    cvt_hilo<<<nx / 1024, 256>>>(x, xh, xl, nx);
    cvt_hilo4<<<dim3(nw / 1024, 4), 256>>>(
        Wq, wqh, wql, Wk, wkh, wkl, Wv, wvh, wvl, Wo, woh, wol, nw);

    dim3 qkvgrid(DIMN / 128, SEQ / 128, 3);   // (16, 28, 3)
    gemm_qkv<<<qkvgrid, 256, GEMM_SMEM_BYTES>>>(
        xh, xl, wqh, wql, wkh, wkl, wvh, wvl, bq, bk, bv, pq, pk, vh, vl);

    rms_rope<<<dim3(SEQ, 2), 256>>>(pq, pk, qh, ql, kh, kl, gq, gk, freqs);

    reset_ctr<<<1, 1>>>();
    flash_hmma<<<148, 256, FLASH3_SMEM>>>(qh, ql, kh, kl, vh, vl, oh, ol);

    dim3 ogrid(DIMN / 128, SEQ / 128);        // (16, 28)
    gemm_out<<<ogrid, 256, GEMM_SMEM_BYTES>>>(oh, ol, woh, wol, bo, out);
}

// round 13
// speedup vs baseline: 1.5386x; 1.5386x over previous
#include <cuda_runtime.h>
#include <cuda_bf16.h>
#include <cstdint>
#include <cstddef>

#define SEQ  3584
#define DIMN 2048
#define NHEAD 16
#define HD   128
#define MQ   3072

// ---------------------------------------------------------------------------
// Scratch (__device__ globals; alloc-free rule)
// ---------------------------------------------------------------------------
__device__ float g_q[SEQ * DIMN];
__device__ float g_k[SEQ * DIMN];

__device__ __nv_bfloat16 g_xh[SEQ * DIMN];
__device__ __nv_bfloat16 g_xl[SEQ * DIMN];
__device__ __nv_bfloat16 g_qh[SEQ * DIMN];
__device__ __nv_bfloat16 g_ql[SEQ * DIMN];
__device__ __nv_bfloat16 g_kh[SEQ * DIMN];
__device__ __nv_bfloat16 g_kl[SEQ * DIMN];
__device__ __nv_bfloat16 g_vh[SEQ * DIMN];
__device__ __nv_bfloat16 g_vl[SEQ * DIMN];
__device__ __nv_bfloat16 g_oh[SEQ * DIMN];
__device__ __nv_bfloat16 g_ol[SEQ * DIMN];
__device__ __nv_bfloat16 g_wqh[DIMN * DIMN];
__device__ __nv_bfloat16 g_wql[DIMN * DIMN];
__device__ __nv_bfloat16 g_wkh[DIMN * DIMN];
__device__ __nv_bfloat16 g_wkl[DIMN * DIMN];
__device__ __nv_bfloat16 g_wvh[DIMN * DIMN];
__device__ __nv_bfloat16 g_wvl[DIMN * DIMN];
__device__ __nv_bfloat16 g_woh[DIMN * DIMN];
__device__ __nv_bfloat16 g_wol[DIMN * DIMN];

// Single extern-shared symbol (shared by all kernels; cast locally)
extern __shared__ __align__(1024) char smem_dyn[];

// ---------------------------------------------------------------------------
// PTX helpers (baseline-PTX only; no tcgen05 on this build path)
// ---------------------------------------------------------------------------
__device__ __forceinline__ uint32_t smem_u32(const void* p) {
    uint32_t a;
    asm("{ .reg .u64 t; cvta.to.shared.u64 t, %1; cvt.u32.u64 %0, t; }"
        : "=r"(a) : "l"(p));
    return a;
}

__device__ __forceinline__ void cp16(uint32_t saddr, const void* gptr) {
    asm volatile("cp.async.cg.shared.global [%0], [%1], 16;" :: "r"(saddr), "l"(gptr));
}
#define CP_COMMIT() asm volatile("cp.async.commit_group;" ::: "memory")
#define CP_WAIT(n)  asm volatile("cp.async.wait_group %0;" :: "n"(n) : "memory")

__device__ __forceinline__ void ldm_x4(uint32_t (&r)[4], uint32_t addr) {
    asm volatile("ldmatrix.sync.aligned.m8n8.x4.shared.b16 {%0,%1,%2,%3}, [%4];"
        : "=r"(r[0]), "=r"(r[1]), "=r"(r[2]), "=r"(r[3]) : "r"(addr));
}
__device__ __forceinline__ void ldm_x4_t(uint32_t (&r)[4], uint32_t addr) {
    asm volatile("ldmatrix.sync.aligned.m8n8.x4.trans.shared.b16 {%0,%1,%2,%3}, [%4];"
        : "=r"(r[0]), "=r"(r[1]), "=r"(r[2]), "=r"(r[3]) : "r"(addr));
}

__device__ __forceinline__ void mma_bf16(float (&d)[4], const uint32_t (&a)[4],
                                         uint32_t b0, uint32_t b1) {
    asm volatile(
        "mma.sync.aligned.m16n8k16.row.col.f32.bf16.bf16.f32 "
        "{%0,%1,%2,%3}, {%4,%5,%6,%7}, {%8,%9}, {%0,%1,%2,%3};"
        : "+f"(d[0]), "+f"(d[1]), "+f"(d[2]), "+f"(d[3])
        : "r"(a[0]), "r"(a[1]), "r"(a[2]), "r"(a[3]), "r"(b0), "r"(b1));
}

__device__ __forceinline__ void splitpack(float a, float b, uint32_t& hi, uint32_t& lo) {
    __nv_bfloat16 ha = __float2bfloat16(a), hb = __float2bfloat16(b);
    __nv_bfloat16 la = __float2bfloat16(a - __bfloat162float(ha));
    __nv_bfloat16 lb = __float2bfloat16(b - __bfloat162float(hb));
    __nv_bfloat162 h2(ha, hb), l2(la, lb);
    hi = *(uint32_t*)&h2;
    lo = *(uint32_t*)&l2;
}

// ---------------------------------------------------------------------------
// fp32 -> bf16 hi/lo split (single + 4-way batched for weights)
// ---------------------------------------------------------------------------
__device__ __forceinline__ void cvt_body(const float* __restrict__ in,
                                         __nv_bfloat16* __restrict__ hi,
                                         __nv_bfloat16* __restrict__ lo, int i)
{
    float4 v = *(const float4*)&in[i];
    float f[4] = {v.x, v.y, v.z, v.w};
    __nv_bfloat16 h[4], l[4];
#pragma unroll
    for (int c = 0; c < 4; c++) {
        h[c] = __float2bfloat16(f[c]);
        l[c] = __float2bfloat16(f[c] - __bfloat162float(h[c]));
    }
    *(__nv_bfloat162*)&hi[i]     = __nv_bfloat162(h[0], h[1]);
    *(__nv_bfloat162*)&hi[i + 2] = __nv_bfloat162(h[2], h[3]);
    *(__nv_bfloat162*)&lo[i]     = __nv_bfloat162(l[0], l[1]);
    *(__nv_bfloat162*)&lo[i + 2] = __nv_bfloat162(l[2], l[3]);
}

__global__ void __launch_bounds__(256) cvt_hilo(const float* __restrict__ in,
                                                __nv_bfloat16* __restrict__ hi,
                                                __nv_bfloat16* __restrict__ lo,
                                                int n)
{
    int i = (blockIdx.x * 256 + threadIdx.x) * 4;
    if (i < n) cvt_body(in, hi, lo, i);
}

__global__ void __launch_bounds__(256) cvt_hilo4(
    const float* __restrict__ i0, __nv_bfloat16* h0, __nv_bfloat16* l0,
    const float* __restrict__ i1, __nv_bfloat16* h1, __nv_bfloat16* l1,
    const float* __restrict__ i2, __nv_bfloat16* h2, __nv_bfloat16* l2,
    const float* __restrict__ i3, __nv_bfloat16* h3, __nv_bfloat16* l3,
    int n)
{
    int i = (blockIdx.x * 256 + threadIdx.x) * 4;
    if (i >= n) return;
    const float* in = (blockIdx.y == 0) ? i0 : (blockIdx.y == 1) ? i1
                    : (blockIdx.y == 2) ? i2 : i3;
    __nv_bfloat16* hi = (blockIdx.y == 0) ? h0 : (blockIdx.y == 1) ? h1
                      : (blockIdx.y == 2) ? h2 : h3;
    __nv_bfloat16* lo = (blockIdx.y == 0) ? l0 : (blockIdx.y == 1) ? l1
                      : (blockIdx.y == 2) ? l2 : l3;
    cvt_body(in, hi, lo, i);
}

// ---------------------------------------------------------------------------
// HMMA GEMM core (R9 config): CTA tile 128x128, BK=32, 256 threads = 8 warps
// (2m x 4n), warp tile 64x32, double-buffered cp.async, split-bf16 3-term.
// ---------------------------------------------------------------------------
#define GBK     32
#define GPITCH  40
#define TILE_E  (128 * GPITCH)
#define STAGE_E (4 * TILE_E)
#define GEMM_SMEM_BYTES (2 * STAGE_E * 2)   // 81920 -> 2 CTAs/SM

struct GemmOut {
    float* f;
    __nv_bfloat16* hi;
    __nv_bfloat16* lo;
};

__device__ __forceinline__ void gemm_body(
    const __nv_bfloat16* __restrict__ Ah, const __nv_bfloat16* __restrict__ Al,
    const __nv_bfloat16* __restrict__ Bh, const __nv_bfloat16* __restrict__ Bl,
    const float* __restrict__ bias, GemmOut out)
{
    __nv_bfloat16* sm = (__nv_bfloat16*)smem_dyn;
    const int tid  = threadIdx.x;
    const int lane = tid & 31;
    const int wid  = tid >> 5;
    const int m0 = blockIdx.y * 128;
    const int n0 = blockIdx.x * 128;
    const int wm0 = (wid & 1) * 64;
    const int wn0 = (wid >> 1) * 32;

    const __nv_bfloat16* srcs[4] = {Ah, Al, Bh, Bl};

    auto load_stage = [&](int stage, int it) {
        const int k0 = it * GBK;
        __nv_bfloat16* st = sm + stage * STAGE_E;
#pragma unroll
        for (int t = 0; t < 4; t++) {
            const __nv_bfloat16* src = srcs[t] + (size_t)(t < 2 ? m0 : n0) * DIMN + k0;
            __nv_bfloat16* tb = st + t * TILE_E;
#pragma unroll
            for (int i = 0; i < 2; i++) {
                int idx = tid + i * 256;
                int row = idx >> 2, ch = idx & 3;
                cp16(smem_u32(tb + row * GPITCH + ch * 8),
                     src + (size_t)row * DIMN + ch * 8);
            }
        }
    };

    float acc[4][4][4];
#pragma unroll
    for (int a = 0; a < 4; a++)
#pragma unroll
        for (int b = 0; b < 4; b++)
#pragma unroll
            for (int c = 0; c < 4; c++) acc[a][b][c] = 0.f;

    load_stage(0, 0);
    CP_COMMIT();

    const int arow = (lane & 7) + ((lane >> 3) & 1) * 8;
    const int acol = (lane >> 4) * 8;
    const int brow = (lane & 7) + (lane >> 4) * 8;
    const int bcol = ((lane >> 3) & 1) * 8;

    const int NIT = DIMN / GBK;
    for (int it = 0; it < NIT; it++) {
        const int b = it & 1;
        if (it + 1 < NIT) { load_stage(1 - b, it + 1); CP_COMMIT(); CP_WAIT(1); }
        else              { CP_WAIT(0); }
        __syncthreads();

        const __nv_bfloat16* sAh = sm + b * STAGE_E;
        const __nv_bfloat16* sAl = sAh + TILE_E;
        const __nv_bfloat16* sBh = sAh + 2 * TILE_E;
        const __nv_bfloat16* sBl = sAh + 3 * TILE_E;

#pragma unroll
        for (int ks = 0; ks < 2; ks++) {
            uint32_t fa[4][4], fbh[2][4], fbl[2][4];
#pragma unroll
            for (int mf = 0; mf < 4; mf++)
                ldm_x4(fa[mf], smem_u32(sAh + (wm0 + mf * 16 + arow) * GPITCH + ks * 16 + acol));
#pragma unroll
            for (int nf = 0; nf < 2; nf++)
                ldm_x4(fbh[nf], smem_u32(sBh + (wn0 + nf * 16 + brow) * GPITCH + ks * 16 + bcol));
#pragma unroll
            for (int mf = 0; mf < 4; mf++)
#pragma unroll
                for (int nf = 0; nf < 4; nf++)
                    mma_bf16(acc[mf][nf], fa[mf], fbh[nf >> 1][(nf & 1) * 2], fbh[nf >> 1][(nf & 1) * 2 + 1]);
#pragma unroll
            for (int nf = 0; nf < 2; nf++)
                ldm_x4(fbl[nf], smem_u32(sBl + (wn0 + nf * 16 + brow) * GPITCH + ks * 16 + bcol));
#pragma unroll
            for (int mf = 0; mf < 4; mf++)
#pragma unroll
                for (int nf = 0; nf < 4; nf++)
                    mma_bf16(acc[mf][nf], fa[mf], fbl[nf >> 1][(nf & 1) * 2], fbl[nf >> 1][(nf & 1) * 2 + 1]);
#pragma unroll
            for (int mf = 0; mf < 4; mf++)
                ldm_x4(fa[mf], smem_u32(sAl + (wm0 + mf * 16 + arow) * GPITCH + ks * 16 + acol));
#pragma unroll
            for (int mf = 0; mf < 4; mf++)
#pragma unroll
                for (int nf = 0; nf < 4; nf++)
                    mma_bf16(acc[mf][nf], fa[mf], fbh[nf >> 1][(nf & 1) * 2], fbh[nf >> 1][(nf & 1) * 2 + 1]);
        }
        __syncthreads();
    }

#pragma unroll
    for (int mf = 0; mf < 4; mf++) {
#pragma unroll
        for (int nf = 0; nf < 4; nf++) {
            int row = m0 + wm0 + mf * 16 + (lane >> 2);
            int col = n0 + wn0 + nf * 8 + (lane & 3) * 2;
            float b0 = bias[col], b1 = bias[col + 1];
            float f00 = acc[mf][nf][0] + b0, f01 = acc[mf][nf][1] + b1;
            float f10 = acc[mf][nf][2] + b0, f11 = acc[mf][nf][3] + b1;
            if (out.hi) {
                uint32_t h0, l0, h1, l1;
                splitpack(f00, f01, h0, l0);
                splitpack(f10, f11, h1, l1);
                *(uint32_t*)&out.hi[(size_t)row * DIMN + col]       = h0;
                *(uint32_t*)&out.lo[(size_t)row * DIMN + col]       = l0;
                *(uint32_t*)&out.hi[(size_t)(row + 8) * DIMN + col] = h1;
                *(uint32_t*)&out.lo[(size_t)(row + 8) * DIMN + col] = l1;
            } else {
                *(float2*)&out.f[(size_t)row * DIMN + col]       = make_float2(f00, f01);
                *(float2*)&out.f[(size_t)(row + 8) * DIMN + col] = make_float2(f10, f11);
            }
        }
    }
}

__global__ void __launch_bounds__(256) gemm_qkv(
    const __nv_bfloat16* __restrict__ xh, const __nv_bfloat16* __restrict__ xl,
    const __nv_bfloat16* __restrict__ wqh, const __nv_bfloat16* __restrict__ wql,
    const __nv_bfloat16* __restrict__ wkh, const __nv_bfloat16* __restrict__ wkl,
    const __nv_bfloat16* __restrict__ wvh, const __nv_bfloat16* __restrict__ wvl,
    const float* __restrict__ bq, const float* __restrict__ bk,
    const float* __restrict__ bv,
    float* outq, float* outk,
    __nv_bfloat16* vh_out, __nv_bfloat16* vl_out)
{
    const int z = blockIdx.z;
    const __nv_bfloat16* Bh = (z == 0) ? wqh : (z == 1) ? wkh : wvh;
    const __nv_bfloat16* Bl = (z == 0) ? wql : (z == 1) ? wkl : wvl;
    const float* bias = (z == 0) ? bq : (z == 1) ? bk : bv;
    GemmOut out;
    if (z == 2) { out.f = nullptr; out.hi = vh_out; out.lo = vl_out; }
    else        { out.f = z ? outk : outq; out.hi = nullptr; out.lo = nullptr; }
    gemm_body(xh, xl, Bh, Bl, bias, out);
}

__global__ void __launch_bounds__(256) gemm_out(
    const __nv_bfloat16* __restrict__ Ah, const __nv_bfloat16* __restrict__ Al,
    const __nv_bfloat16* __restrict__ Bh, const __nv_bfloat16* __restrict__ Bl,
    const float* __restrict__ bias, float* __restrict__ C)
{
    GemmOut out; out.f = C; out.hi = nullptr; out.lo = nullptr;
    gemm_body(Ah, Al, Bh, Bl, bias, out);
}

// ---------------------------------------------------------------------------
// RMSNorm + RoPE; reads fp32 q/k, writes bf16 hi/lo.
// q pre-scaled by log2(e)/sqrt(HD) so flash softmax uses exp2.
// ---------------------------------------------------------------------------
__global__ void __launch_bounds__(256) rms_rope(
    const float* __restrict__ qf, const float* __restrict__ kf,
    __nv_bfloat16* __restrict__ qh, __nv_bfloat16* __restrict__ ql,
    __nv_bfloat16* __restrict__ kh, __nv_bfloat16* __restrict__ kl,
    const float* __restrict__ gq, const float* __restrict__ gk,
    const float* __restrict__ freqs)
{
    const int row = blockIdx.x;
    const int which = blockIdx.y;
    const float* rowp = (which ? kf : qf) + (size_t)row * DIMN;
    __nv_bfloat16* oh = (which ? kh : qh) + (size_t)row * DIMN;
    __nv_bfloat16* ol = (which ? kl : ql) + (size_t)row * DIMN;
    const float* g = which ? gk : gq;
    const int tid = threadIdx.x;
    const float outscale = which ? 1.0f
        : (0.08838834764831845f * 1.4426950408889634f);   // log2(e)/sqrt(128)

    float ss = 0.f;
    for (int i = tid; i < DIMN; i += 256) { float v = rowp[i]; ss += v * v; }
#pragma unroll
    for (int o = 16; o > 0; o >>= 1) ss += __shfl_xor_sync(0xffffffffu, ss, o);

    __shared__ float wsum[8];
    __shared__ float sinvs;
    if ((tid & 31) == 0) wsum[tid >> 5] = ss;
    __syncthreads();
    if (tid == 0) {
        float t = 0.f;
#pragma unroll
        for (int i = 0; i < 8; i++) t += wsum[i];
        sinvs = rsqrtf(t * (1.0f / (float)DIMN) + 1e-6f);
    }
    __syncthreads();
    const float inv = sinvs;

    int f, h, w;
    if (row < MQ) { f = row >> 8; int rem = row & 255; h = rem >> 4; w = rem & 15; }
    else { int rr = row - MQ; f = 12 + (rr >> 8); int rem = rr & 255; h = rem >> 4; w = rem & 15; }

    for (int p = tid; p < DIMN / 2; p += 256) {
        int hp = p & 63;
        int pos = (hp < 22) ? f : ((hp < 43) ? h : w);
        float c = freqs[(pos * 64 + hp) * 2 + 0];
        float s = freqs[(pos * 64 + hp) * 2 + 1];
        float e = rowp[2 * p]     * inv * g[2 * p];
        float o = rowp[2 * p + 1] * inv * g[2 * p + 1];
        float r0 = (e * c - o * s) * outscale;
        float r1 = (e * s + o * c) * outscale;
        uint32_t hi, lo;
        splitpack(r0, r1, hi, lo);
        *(uint32_t*)&oh[2 * p] = hi;
        *(uint32_t*)&ol[2 * p] = lo;
    }
}

// ---------------------------------------------------------------------------
// HMMA flash attention (R9 rigid-grid config). CTA: 256 threads (8 warps),
// Q tile 128 x 128, warp = 16 q-rows, K/V 64-row tiles double-buffered via
// cp.async; softmax (exp2 domain) in registers; P in registers; bf16 hi/lo out.
// ---------------------------------------------------------------------------
#define FP2 136
#define FQH_B 0
#define FQL_B 34816
#define FSTG_B 69632
#define FSTG_SZ 69632
#define FKH_B 0
#define FKL_B 17408
#define FVH_B 34816
#define FVL_B 52224
#define FLASH3_SMEM (FSTG_B + 2 * FSTG_SZ)   // 208896

__global__ void __launch_bounds__(256, 1) flash_hmma(
    const __nv_bfloat16* __restrict__ qh, const __nv_bfloat16* __restrict__ ql,
    const __nv_bfloat16* __restrict__ kh, const __nv_bfloat16* __restrict__ kl,
    const __nv_bfloat16* __restrict__ vh, const __nv_bfloat16* __restrict__ vl,
    __nv_bfloat16* __restrict__ ohp, __nv_bfloat16* __restrict__ olp)
{
    const uint32_t sb = smem_u32(smem_dyn);
    const int tid  = threadIdx.x;
    const int lane = tid & 31;
    const int wid  = tid >> 5;
    const int qt   = blockIdx.x;
    const int head = blockIdx.y;
    const int q0   = qt * 128;
    const int hoff = head * HD;
    const int wrow = wid * 16;

    const int arow = (lane & 7) + ((lane >> 3) & 1) * 8;
    const int acol = (lane >> 4) * 8;
    const int brow = (lane & 7) + (lane >> 4) * 8;
    const int bcol = ((lane >> 3) & 1) * 8;

    for (int i = tid; i < 128 * 16; i += 256) {
        int row = i >> 4, ch = i & 15;
        size_t goff = (size_t)(q0 + row) * DIMN + hoff + ch * 8;
        uint32_t soff = (uint32_t)(row * FP2 + ch * 8) * 2;
        cp16(sb + FQH_B + soff, qh + goff);
        cp16(sb + FQL_B + soff, ql + goff);
    }

    auto load_kv = [&](int stage, int kt) {
        const int k0 = kt * 64;
        const uint32_t stb = sb + FSTG_B + stage * FSTG_SZ;
        for (int i = tid; i < 64 * 16; i += 256) {
            int row = i >> 4, ch = i & 15;
            size_t goff = (size_t)(k0 + row) * DIMN + hoff + ch * 8;
            uint32_t soff = (uint32_t)(row * FP2 + ch * 8) * 2;
            cp16(stb + FKH_B + soff, kh + goff);
            cp16(stb + FKL_B + soff, kl + goff);
            cp16(stb + FVH_B + soff, vh + goff);
            cp16(stb + FVL_B + soff, vl + goff);
        }
    };

    int ktb, kte;
    if (qt < 24) { ktb = 0; kte = 56; }
    else { int j = (qt - 24) >> 1; ktb = 48 + j * 4; kte = ktb + 4; }
    const int nkt = kte - ktb;

    load_kv(0, ktb);
    CP_COMMIT();

    float o[16][4];
#pragma unroll
    for (int i = 0; i < 16; i++)
#pragma unroll
        for (int j = 0; j < 4; j++) o[i][j] = 0.f;
    float mrun0 = -1e30f, mrun1 = -1e30f;
    float lrun0 = 0.f, lrun1 = 0.f;

    for (int i = 0; i < nkt; i++) {
        if (i + 1 < nkt) { load_kv((i + 1) & 1, ktb + i + 1); CP_COMMIT(); CP_WAIT(1); }
        else             { CP_WAIT(0); }
        __syncthreads();
        const uint32_t stb = sb + FSTG_B + (i & 1) * FSTG_SZ;

        float s[8][4];
#pragma unroll
        for (int nf = 0; nf < 8; nf++)
#pragma unroll
            for (int c = 0; c < 4; c++) s[nf][c] = 0.f;

#pragma unroll
        for (int kc = 0; kc < 8; kc++) {
            uint32_t fqh_[4], fql_[4], fkh_[4][4], fkl_[4][4];
            uint32_t aoff = (uint32_t)((wrow + arow) * FP2 + kc * 16 + acol) * 2;
            ldm_x4(fqh_, sb + FQH_B + aoff);
            ldm_x4(fql_, sb + FQL_B + aoff);
#pragma unroll
            for (int b = 0; b < 4; b++) {
                uint32_t boff = (uint32_t)((b * 16 + brow) * FP2 + kc * 16 + bcol) * 2;
                ldm_x4(fkh_[b], stb + FKH_B + boff);
                ldm_x4(fkl_[b], stb + FKL_B + boff);
            }
#pragma unroll
            for (int nf = 0; nf < 8; nf++) {
                uint32_t bh0 = fkh_[nf >> 1][(nf & 1) * 2], bh1 = fkh_[nf >> 1][(nf & 1) * 2 + 1];
                uint32_t bl0 = fkl_[nf >> 1][(nf & 1) * 2], bl1 = fkl_[nf >> 1][(nf & 1) * 2 + 1];
                mma_bf16(s[nf], fqh_, bh0, bh1);
                mma_bf16(s[nf], fqh_, bl0, bl1);
                mma_bf16(s[nf], fql_, bh0, bh1);
            }
        }

        float mx0 = -1e30f, mx1 = -1e30f;
#pragma unroll
        for (int nf = 0; nf < 8; nf++) {
            mx0 = fmaxf(mx0, fmaxf(s[nf][0], s[nf][1]));
            mx1 = fmaxf(mx1, fmaxf(s[nf][2], s[nf][3]));
        }
        mx0 = fmaxf(mx0, __shfl_xor_sync(0xffffffffu, mx0, 1));
        mx0 = fmaxf(mx0, __shfl_xor_sync(0xffffffffu, mx0, 2));
        mx1 = fmaxf(mx1, __shfl_xor_sync(0xffffffffu, mx1, 1));
        mx1 = fmaxf(mx1, __shfl_xor_sync(0xffffffffu, mx1, 2));
        float m0 = fmaxf(mrun0, mx0), m1 = fmaxf(mrun1, mx1);
        float a0 = exp2f(mrun0 - m0), a1 = exp2f(mrun1 - m1);
        mrun0 = m0; mrun1 = m1;

        float sum0 = 0.f, sum1 = 0.f;
#pragma unroll
        for (int nf = 0; nf < 8; nf++) {
            s[nf][0] = exp2f(s[nf][0] - m0);
            s[nf][1] = exp2f(s[nf][1] - m0);
            s[nf][2] = exp2f(s[nf][2] - m1);
            s[nf][3] = exp2f(s[nf][3] - m1);
            sum0 += s[nf][0] + s[nf][1];
            sum1 += s[nf][2] + s[nf][3];
        }
        sum0 += __shfl_xor_sync(0xffffffffu, sum0, 1);
        sum0 += __shfl_xor_sync(0xffffffffu, sum0, 2);
        sum1 += __shfl_xor_sync(0xffffffffu, sum1, 1);
        sum1 += __shfl_xor_sync(0xffffffffu, sum1, 2);
        lrun0 = lrun0 * a0 + sum0;
        lrun1 = lrun1 * a1 + sum1;

#pragma unroll
        for (int nf = 0; nf < 16; nf++) {
            o[nf][0] *= a0; o[nf][1] *= a0;
            o[nf][2] *= a1; o[nf][3] *= a1;
        }

        uint32_t pha[4][4], pla[4][4];
#pragma unroll
        for (int c2 = 0; c2 < 4; c2++) {
            splitpack(s[2 * c2][0],     s[2 * c2][1],     pha[c2][0], pla[c2][0]);
            splitpack(s[2 * c2][2],     s[2 * c2][3],     pha[c2][1], pla[c2][1]);
            splitpack(s[2 * c2 + 1][0], s[2 * c2 + 1][1], pha[c2][2], pla[c2][2]);
            splitpack(s[2 * c2 + 1][2], s[2 * c2 + 1][3], pha[c2][3], pla[c2][3]);
        }

#pragma unroll
        for (int c2 = 0; c2 < 4; c2++) {
#pragma unroll
            for (int db = 0; db < 8; db++) {
                uint32_t fvh_[4], fvl_[4];
                uint32_t voff = (uint32_t)((c2 * 16 + arow) * FP2 + db * 16 + acol) * 2;
                ldm_x4_t(fvh_, stb + FVH_B + voff);
                ldm_x4_t(fvl_, stb + FVL_B + voff);
                mma_bf16(o[2 * db],     pha[c2], fvh_[0], fvh_[1]);
                mma_bf16(o[2 * db + 1], pha[c2], fvh_[2], fvh_[3]);
                mma_bf16(o[2 * db],     pha[c2], fvl_[0], fvl_[1]);
                mma_bf16(o[2 * db + 1], pha[c2], fvl_[2], fvl_[3]);
                mma_bf16(o[2 * db],     pla[c2], fvh_[0], fvh_[1]);
                mma_bf16(o[2 * db + 1], pla[c2], fvh_[2], fvh_[3]);
            }
        }
        __syncthreads();
    }

    float inv0 = 1.0f / lrun0, inv1 = 1.0f / lrun1;
    int r0 = q0 + wrow + (lane >> 2);
    int r1 = r0 + 8;
    int cbase = hoff + (lane & 3) * 2;
#pragma unroll
    for (int nf = 0; nf < 16; nf++) {
        int col = cbase + nf * 8;
        float f0 = o[nf][0] * inv0, f1 = o[nf][1] * inv0;
        float f2 = o[nf][2] * inv1, f3 = o[nf][3] * inv1;
        uint32_t h01, l01, h23, l23;
        splitpack(f0, f1, h01, l01);
        splitpack(f2, f3, h23, l23);
        *(uint32_t*)&ohp[(size_t)r0 * DIMN + col] = h01;
        *(uint32_t*)&olp[(size_t)r0 * DIMN + col] = l01;
        *(uint32_t*)&ohp[(size_t)r1 * DIMN + col] = h23;
        *(uint32_t*)&olp[(size_t)r1 * DIMN + col] = l23;
    }
}

// ---------------------------------------------------------------------------
// Launch
// ---------------------------------------------------------------------------
extern "C" void kernel_launch(void* const* d_in, const int* in_sizes, int n_in,
                              void* d_out, int out_size)
{
    (void)in_sizes; (void)n_in; (void)out_size;
    const float* x     = (const float*)d_in[0];
    const float* Wq    = (const float*)d_in[1];
    const float* bq    = (const float*)d_in[2];
    const float* Wk    = (const float*)d_in[3];
    const float* bk    = (const float*)d_in[4];
    const float* Wv    = (const float*)d_in[5];
    const float* bv    = (const float*)d_in[6];
    const float* Wo    = (const float*)d_in[7];
    const float* bo    = (const float*)d_in[8];
    const float* gq    = (const float*)d_in[9];
    const float* gk    = (const float*)d_in[10];
    const float* freqs = (const float*)d_in[11];
    float* out = (float*)d_out;

    float *pq, *pk;
    cudaGetSymbolAddress((void**)&pq, g_q);
    cudaGetSymbolAddress((void**)&pk, g_k);

    __nv_bfloat16 *xh, *xl, *oh, *ol;
    __nv_bfloat16 *qh, *ql, *kh, *kl, *vh, *vl;
    __nv_bfloat16 *wqh, *wql, *wkh, *wkl, *wvh, *wvl, *woh, *wol;
    cudaGetSymbolAddress((void**)&xh, g_xh);   cudaGetSymbolAddress((void**)&xl, g_xl);
    cudaGetSymbolAddress((void**)&oh, g_oh);   cudaGetSymbolAddress((void**)&ol, g_ol);
    cudaGetSymbolAddress((void**)&qh, g_qh);   cudaGetSymbolAddress((void**)&ql, g_ql);
    cudaGetSymbolAddress((void**)&kh, g_kh);   cudaGetSymbolAddress((void**)&kl, g_kl);
    cudaGetSymbolAddress((void**)&vh, g_vh);   cudaGetSymbolAddress((void**)&vl, g_vl);
    cudaGetSymbolAddress((void**)&wqh, g_wqh); cudaGetSymbolAddress((void**)&wql, g_wql);
    cudaGetSymbolAddress((void**)&wkh, g_wkh); cudaGetSymbolAddress((void**)&wkl, g_wkl);
    cudaGetSymbolAddress((void**)&wvh, g_wvh); cudaGetSymbolAddress((void**)&wvl, g_wvl);
    cudaGetSymbolAddress((void**)&woh, g_woh); cudaGetSymbolAddress((void**)&wol, g_wol);

    cudaFuncSetAttribute(gemm_qkv, cudaFuncAttributeMaxDynamicSharedMemorySize,
                         GEMM_SMEM_BYTES);
    cudaFuncSetAttribute(gemm_out, cudaFuncAttributeMaxDynamicSharedMemorySize,
                         GEMM_SMEM_BYTES);
    cudaFuncSetAttribute(flash_hmma, cudaFuncAttributeMaxDynamicSharedMemorySize,
                         FLASH3_SMEM);

    const int nx = SEQ * DIMN, nw = DIMN * DIMN;
    cvt_hilo<<<nx / 1024, 256>>>(x, xh, xl, nx);
    cvt_hilo4<<<dim3(nw / 1024, 4), 256>>>(
        Wq, wqh, wql, Wk, wkh, wkl, Wv, wvh, wvl, Wo, woh, wol, nw);

    dim3 qkvgrid(DIMN / 128, SEQ / 128, 3);   // (16, 28, 3)
    gemm_qkv<<<qkvgrid, 256, GEMM_SMEM_BYTES>>>(
        xh, xl, wqh, wql, wkh, wkl, wvh, wvl, bq, bk, bv, pq, pk, vh, vl);

    rms_rope<<<dim3(SEQ, 2), 256>>>(pq, pk, qh, ql, kh, kl, gq, gk, freqs);

    flash_hmma<<<dim3(SEQ / 128, NHEAD), 256, FLASH3_SMEM>>>(
        qh, ql, kh, kl, vh, vl, oh, ol);

    dim3 ogrid(DIMN / 128, SEQ / 128);        // (16, 28)
    gemm_out<<<ogrid, 256, GEMM_SMEM_BYTES>>>(oh, ol, woh, wol, bo, out);
}

// round 15
// speedup vs baseline: 1.5444x; 1.0038x over previous
#include <cuda_runtime.h>
#include <cuda_bf16.h>
#include <cstdint>
#include <cstddef>

#define SEQ  3584
#define DIMN 2048
#define NHEAD 16
#define HD   128
#define MQ   3072

// ---------------------------------------------------------------------------
// Scratch (__device__ globals; alloc-free rule)
// ---------------------------------------------------------------------------
__device__ float g_q[SEQ * DIMN];
__device__ float g_k[SEQ * DIMN];

__device__ __nv_bfloat16 g_xh[SEQ * DIMN];
__device__ __nv_bfloat16 g_xl[SEQ * DIMN];
__device__ __nv_bfloat16 g_qh[SEQ * DIMN];
__device__ __nv_bfloat16 g_ql[SEQ * DIMN];
__device__ __nv_bfloat16 g_kh[SEQ * DIMN];
__device__ __nv_bfloat16 g_kl[SEQ * DIMN];
__device__ __nv_bfloat16 g_vh[SEQ * DIMN];
__device__ __nv_bfloat16 g_vl[SEQ * DIMN];
__device__ __nv_bfloat16 g_oh[SEQ * DIMN];
__device__ __nv_bfloat16 g_ol[SEQ * DIMN];
__device__ __nv_bfloat16 g_wqh[DIMN * DIMN];
__device__ __nv_bfloat16 g_wql[DIMN * DIMN];
__device__ __nv_bfloat16 g_wkh[DIMN * DIMN];
__device__ __nv_bfloat16 g_wkl[DIMN * DIMN];
__device__ __nv_bfloat16 g_wvh[DIMN * DIMN];
__device__ __nv_bfloat16 g_wvl[DIMN * DIMN];
__device__ __nv_bfloat16 g_woh[DIMN * DIMN];
__device__ __nv_bfloat16 g_wol[DIMN * DIMN];

// Single extern-shared symbol (shared by all kernels; cast locally)
extern __shared__ __align__(1024) char smem_dyn[];

// ---------------------------------------------------------------------------
// PTX helpers (baseline-PTX only; no tcgen05 on this build path)
// ---------------------------------------------------------------------------
__device__ __forceinline__ uint32_t smem_u32(const void* p) {
    uint32_t a;
    asm("{ .reg .u64 t; cvta.to.shared.u64 t, %1; cvt.u32.u64 %0, t; }"
        : "=r"(a) : "l"(p));
    return a;
}

__device__ __forceinline__ void cp16(uint32_t saddr, const void* gptr) {
    asm volatile("cp.async.cg.shared.global [%0], [%1], 16;" :: "r"(saddr), "l"(gptr));
}
#define CP_COMMIT() asm volatile("cp.async.commit_group;" ::: "memory")
#define CP_WAIT(n)  asm volatile("cp.async.wait_group %0;" :: "n"(n) : "memory")

__device__ __forceinline__ void ldm_x4(uint32_t (&r)[4], uint32_t addr) {
    asm volatile("ldmatrix.sync.aligned.m8n8.x4.shared.b16 {%0,%1,%2,%3}, [%4];"
        : "=r"(r[0]), "=r"(r[1]), "=r"(r[2]), "=r"(r[3]) : "r"(addr));
}
__device__ __forceinline__ void ldm_x4_t(uint32_t (&r)[4], uint32_t addr) {
    asm volatile("ldmatrix.sync.aligned.m8n8.x4.trans.shared.b16 {%0,%1,%2,%3}, [%4];"
        : "=r"(r[0]), "=r"(r[1]), "=r"(r[2]), "=r"(r[3]) : "r"(addr));
}

__device__ __forceinline__ void mma_bf16(float (&d)[4], const uint32_t (&a)[4],
                                         uint32_t b0, uint32_t b1) {
    asm volatile(
        "mma.sync.aligned.m16n8k16.row.col.f32.bf16.bf16.f32 "
        "{%0,%1,%2,%3}, {%4,%5,%6,%7}, {%8,%9}, {%0,%1,%2,%3};"
        : "+f"(d[0]), "+f"(d[1]), "+f"(d[2]), "+f"(d[3])
        : "r"(a[0]), "r"(a[1]), "r"(a[2]), "r"(a[3]), "r"(b0), "r"(b1));
}

__device__ __forceinline__ void splitpack(float a, float b, uint32_t& hi, uint32_t& lo) {
    __nv_bfloat16 ha = __float2bfloat16(a), hb = __float2bfloat16(b);
    __nv_bfloat16 la = __float2bfloat16(a - __bfloat162float(ha));
    __nv_bfloat16 lb = __float2bfloat16(b - __bfloat162float(hb));
    __nv_bfloat162 h2(ha, hb), l2(la, lb);
    hi = *(uint32_t*)&h2;
    lo = *(uint32_t*)&l2;
}

// ---------------------------------------------------------------------------
// fp32 -> bf16 hi/lo split; 5-way batched (x + 4 weight matrices)
// ---------------------------------------------------------------------------
__device__ __forceinline__ void cvt_body(const float* __restrict__ in,
                                         __nv_bfloat16* __restrict__ hi,
                                         __nv_bfloat16* __restrict__ lo, int i)
{
    float4 v = *(const float4*)&in[i];
    float f[4] = {v.x, v.y, v.z, v.w};
    __nv_bfloat16 h[4], l[4];
#pragma unroll
    for (int c = 0; c < 4; c++) {
        h[c] = __float2bfloat16(f[c]);
        l[c] = __float2bfloat16(f[c] - __bfloat162float(h[c]));
    }
    *(__nv_bfloat162*)&hi[i]     = __nv_bfloat162(h[0], h[1]);
    *(__nv_bfloat162*)&hi[i + 2] = __nv_bfloat162(h[2], h[3]);
    *(__nv_bfloat162*)&lo[i]     = __nv_bfloat162(l[0], l[1]);
    *(__nv_bfloat162*)&lo[i + 2] = __nv_bfloat162(l[2], l[3]);
}

__global__ void __launch_bounds__(256) cvt_hilo5(
    const float* __restrict__ i0, __nv_bfloat16* h0, __nv_bfloat16* l0, int n0,
    const float* __restrict__ i1, __nv_bfloat16* h1, __nv_bfloat16* l1,
    const float* __restrict__ i2, __nv_bfloat16* h2, __nv_bfloat16* l2,
    const float* __restrict__ i3, __nv_bfloat16* h3, __nv_bfloat16* l3,
    const float* __restrict__ i4, __nv_bfloat16* h4, __nv_bfloat16* l4, int nw)
{
    int i = (blockIdx.x * 256 + threadIdx.x) * 4;
    int y = blockIdx.y;
    int n = (y == 0) ? n0 : nw;
    if (i >= n) return;
    const float* in = (y == 0) ? i0 : (y == 1) ? i1 : (y == 2) ? i2
                    : (y == 3) ? i3 : i4;
    __nv_bfloat16* hi = (y == 0) ? h0 : (y == 1) ? h1 : (y == 2) ? h2
                      : (y == 3) ? h3 : h4;
    __nv_bfloat16* lo = (y == 0) ? l0 : (y == 1) ? l1 : (y == 2) ? l2
                      : (y == 3) ? l3 : l4;
    cvt_body(in, hi, lo, i);
}

// ---------------------------------------------------------------------------
// HMMA GEMM core (R9 config): CTA tile 128x128, BK=32, 256 threads = 8 warps
// (2m x 4n), warp tile 64x32, double-buffered cp.async, split-bf16 3-term.
// ---------------------------------------------------------------------------
#define GBK     32
#define GPITCH  40
#define TILE_E  (128 * GPITCH)
#define STAGE_E (4 * TILE_E)
#define GEMM_SMEM_BYTES (2 * STAGE_E * 2)   // 81920 -> 2 CTAs/SM

struct GemmOut {
    float* f;
    __nv_bfloat16* hi;
    __nv_bfloat16* lo;
};

__device__ __forceinline__ void gemm_body(
    const __nv_bfloat16* __restrict__ Ah, const __nv_bfloat16* __restrict__ Al,
    const __nv_bfloat16* __restrict__ Bh, const __nv_bfloat16* __restrict__ Bl,
    const float* __restrict__ bias, GemmOut out)
{
    __nv_bfloat16* sm = (__nv_bfloat16*)smem_dyn;
    const int tid  = threadIdx.x;
    const int lane = tid & 31;
    const int wid  = tid >> 5;
    const int m0 = blockIdx.y * 128;
    const int n0 = blockIdx.x * 128;
    const int wm0 = (wid & 1) * 64;
    const int wn0 = (wid >> 1) * 32;

    const __nv_bfloat16* srcs[4] = {Ah, Al, Bh, Bl};

    auto load_stage = [&](int stage, int it) {
        const int k0 = it * GBK;
        __nv_bfloat16* st = sm + stage * STAGE_E;
#pragma unroll
        for (int t = 0; t < 4; t++) {
            const __nv_bfloat16* src = srcs[t] + (size_t)(t < 2 ? m0 : n0) * DIMN + k0;
            __nv_bfloat16* tb = st + t * TILE_E;
#pragma unroll
            for (int i = 0; i < 2; i++) {
                int idx = tid + i * 256;
                int row = idx >> 2, ch = idx & 3;
                cp16(smem_u32(tb + row * GPITCH + ch * 8),
                     src + (size_t)row * DIMN + ch * 8);
            }
        }
    };

    float acc[4][4][4];
#pragma unroll
    for (int a = 0; a < 4; a++)
#pragma unroll
        for (int b = 0; b < 4; b++)
#pragma unroll
            for (int c = 0; c < 4; c++) acc[a][b][c] = 0.f;

    load_stage(0, 0);
    CP_COMMIT();

    const int arow = (lane & 7) + ((lane >> 3) & 1) * 8;
    const int acol = (lane >> 4) * 8;
    const int brow = (lane & 7) + (lane >> 4) * 8;
    const int bcol = ((lane >> 3) & 1) * 8;

    const int NIT = DIMN / GBK;
    for (int it = 0; it < NIT; it++) {
        const int b = it & 1;
        if (it + 1 < NIT) { load_stage(1 - b, it + 1); CP_COMMIT(); CP_WAIT(1); }
        else              { CP_WAIT(0); }
        __syncthreads();

        const __nv_bfloat16* sAh = sm + b * STAGE_E;
        const __nv_bfloat16* sAl = sAh + TILE_E;
        const __nv_bfloat16* sBh = sAh + 2 * TILE_E;
        const __nv_bfloat16* sBl = sAh + 3 * TILE_E;

#pragma unroll
        for (int ks = 0; ks < 2; ks++) {
            uint32_t fa[4][4], fbh[2][4], fbl[2][4];
#pragma unroll
            for (int mf = 0; mf < 4; mf++)
                ldm_x4(fa[mf], smem_u32(sAh + (wm0 + mf * 16 + arow) * GPITCH + ks * 16 + acol));
#pragma unroll
            for (int nf = 0; nf < 2; nf++)
                ldm_x4(fbh[nf], smem_u32(sBh + (wn0 + nf * 16 + brow) * GPITCH + ks * 16 + bcol));
#pragma unroll
            for (int mf = 0; mf < 4; mf++)
#pragma unroll
                for (int nf = 0; nf < 4; nf++)
                    mma_bf16(acc[mf][nf], fa[mf], fbh[nf >> 1][(nf & 1) * 2], fbh[nf >> 1][(nf & 1) * 2 + 1]);
#pragma unroll
            for (int nf = 0; nf < 2; nf++)
                ldm_x4(fbl[nf], smem_u32(sBl + (wn0 + nf * 16 + brow) * GPITCH + ks * 16 + bcol));
#pragma unroll
            for (int mf = 0; mf < 4; mf++)
#pragma unroll
                for (int nf = 0; nf < 4; nf++)
                    mma_bf16(acc[mf][nf], fa[mf], fbl[nf >> 1][(nf & 1) * 2], fbl[nf >> 1][(nf & 1) * 2 + 1]);
#pragma unroll
            for (int mf = 0; mf < 4; mf++)
                ldm_x4(fa[mf], smem_u32(sAl + (wm0 + mf * 16 + arow) * GPITCH + ks * 16 + acol));
#pragma unroll
            for (int mf = 0; mf < 4; mf++)
#pragma unroll
                for (int nf = 0; nf < 4; nf++)
                    mma_bf16(acc[mf][nf], fa[mf], fbh[nf >> 1][(nf & 1) * 2], fbh[nf >> 1][(nf & 1) * 2 + 1]);
        }
        __syncthreads();
    }

#pragma unroll
    for (int mf = 0; mf < 4; mf++) {
#pragma unroll
        for (int nf = 0; nf < 4; nf++) {
            int row = m0 + wm0 + mf * 16 + (lane >> 2);
            int col = n0 + wn0 + nf * 8 + (lane & 3) * 2;
            float b0 = bias[col], b1 = bias[col + 1];
            float f00 = acc[mf][nf][0] + b0, f01 = acc[mf][nf][1] + b1;
            float f10 = acc[mf][nf][2] + b0, f11 = acc[mf][nf][3] + b1;
            if (out.hi) {
                uint32_t h0, l0, h1, l1;
                splitpack(f00, f01, h0, l0);
                splitpack(f10, f11, h1, l1);
                *(uint32_t*)&out.hi[(size_t)row * DIMN + col]       = h0;
                *(uint32_t*)&out.lo[(size_t)row * DIMN + col]       = l0;
                *(uint32_t*)&out.hi[(size_t)(row + 8) * DIMN + col] = h1;
                *(uint32_t*)&out.lo[(size_t)(row + 8) * DIMN + col] = l1;
            } else {
                *(float2*)&out.f[(size_t)row * DIMN + col]       = make_float2(f00, f01);
                *(float2*)&out.f[(size_t)(row + 8) * DIMN + col] = make_float2(f10, f11);
            }
        }
    }
}

__global__ void __launch_bounds__(256) gemm_qkv(
    const __nv_bfloat16* __restrict__ xh, const __nv_bfloat16* __restrict__ xl,
    const __nv_bfloat16* __restrict__ wqh, const __nv_bfloat16* __restrict__ wql,
    const __nv_bfloat16* __restrict__ wkh, const __nv_bfloat16* __restrict__ wkl,
    const __nv_bfloat16* __restrict__ wvh, const __nv_bfloat16* __restrict__ wvl,
    const float* __restrict__ bq, const float* __restrict__ bk,
    const float* __restrict__ bv,
    float* outq, float* outk,
    __nv_bfloat16* vh_out, __nv_bfloat16* vl_out)
{
    const int z = blockIdx.z;
    const __nv_bfloat16* Bh = (z == 0) ? wqh : (z == 1) ? wkh : wvh;
    const __nv_bfloat16* Bl = (z == 0) ? wql : (z == 1) ? wkl : wvl;
    const float* bias = (z == 0) ? bq : (z == 1) ? bk : bv;
    GemmOut out;
    if (z == 2) { out.f = nullptr; out.hi = vh_out; out.lo = vl_out; }
    else        { out.f = z ? outk : outq; out.hi = nullptr; out.lo = nullptr; }
    gemm_body(xh, xl, Bh, Bl, bias, out);
}

__global__ void __launch_bounds__(256) gemm_out(
    const __nv_bfloat16* __restrict__ Ah, const __nv_bfloat16* __restrict__ Al,
    const __nv_bfloat16* __restrict__ Bh, const __nv_bfloat16* __restrict__ Bl,
    const float* __restrict__ bias, float* __restrict__ C)
{
    GemmOut out; out.f = C; out.hi = nullptr; out.lo = nullptr;
    gemm_body(Ah, Al, Bh, Bl, bias, out);
}

// ---------------------------------------------------------------------------
// RMSNorm + RoPE; reads fp32 q/k, writes bf16 hi/lo.
// q pre-scaled by log2(e)/sqrt(HD) so flash softmax uses exp2.
// ---------------------------------------------------------------------------
__global__ void __launch_bounds__(256) rms_rope(
    const float* __restrict__ qf, const float* __restrict__ kf,
    __nv_bfloat16* __restrict__ qh, __nv_bfloat16* __restrict__ ql,
    __nv_bfloat16* __restrict__ kh, __nv_bfloat16* __restrict__ kl,
    const float* __restrict__ gq, const float* __restrict__ gk,
    const float* __restrict__ freqs)
{
    const int row = blockIdx.x;
    const int which = blockIdx.y;
    const float* rowp = (which ? kf : qf) + (size_t)row * DIMN;
    __nv_bfloat16* oh = (which ? kh : qh) + (size_t)row * DIMN;
    __nv_bfloat16* ol = (which ? kl : ql) + (size_t)row * DIMN;
    const float* g = which ? gk : gq;
    const int tid = threadIdx.x;
    const float outscale = which ? 1.0f
        : (0.08838834764831845f * 1.4426950408889634f);   // log2(e)/sqrt(128)

    float ss = 0.f;
    for (int i = tid; i < DIMN; i += 256) { float v = rowp[i]; ss += v * v; }
#pragma unroll
    for (int o = 16; o > 0; o >>= 1) ss += __shfl_xor_sync(0xffffffffu, ss, o);

    __shared__ float wsum[8];
    __shared__ float sinvs;
    if ((tid & 31) == 0) wsum[tid >> 5] = ss;
    __syncthreads();
    if (tid == 0) {
        float t = 0.f;
#pragma unroll
        for (int i = 0; i < 8; i++) t += wsum[i];
        sinvs = rsqrtf(t * (1.0f / (float)DIMN) + 1e-6f);
    }
    __syncthreads();
    const float inv = sinvs;

    int f, h, w;
    if (row < MQ) { f = row >> 8; int rem = row & 255; h = rem >> 4; w = rem & 15; }
    else { int rr = row - MQ; f = 12 + (rr >> 8); int rem = rr & 255; h = rem >> 4; w = rem & 15; }

    for (int p = tid; p < DIMN / 2; p += 256) {
        int hp = p & 63;
        int pos = (hp < 22) ? f : ((hp < 43) ? h : w);
        float c = freqs[(pos * 64 + hp) * 2 + 0];
        float s = freqs[(pos * 64 + hp) * 2 + 1];
        float e = rowp[2 * p]     * inv * g[2 * p];
        float o = rowp[2 * p + 1] * inv * g[2 * p + 1];
        float r0 = (e * c - o * s) * outscale;
        float r1 = (e * s + o * c) * outscale;
        uint32_t hi, lo;
        splitpack(r0, r1, hi, lo);
        *(uint32_t*)&oh[2 * p] = hi;
        *(uint32_t*)&ol[2 * p] = lo;
    }
}

// ---------------------------------------------------------------------------
// HMMA flash attention. CTA: 256 threads (8 warps), Q tile 128 x 128,
// warp = 16 q-rows. Q fragments cached in REGISTERS across the k-loop
// (loaded once). K/V 64-row tiles double-buffered via cp.async; softmax
// (exp2 domain) in registers; P in registers; bf16 hi/lo out.
// ---------------------------------------------------------------------------
#define FP2 136
#define FQH_B 0
#define FQL_B 34816
#define FSTG_B 69632
#define FSTG_SZ 69632
#define FKH_B 0
#define FKL_B 17408
#define FVH_B 34816
#define FVL_B 52224
#define FLASH3_SMEM (FSTG_B + 2 * FSTG_SZ)   // 208896

__global__ void __launch_bounds__(256, 1) flash_hmma(
    const __nv_bfloat16* __restrict__ qh, const __nv_bfloat16* __restrict__ ql,
    const __nv_bfloat16* __restrict__ kh, const __nv_bfloat16* __restrict__ kl,
    const __nv_bfloat16* __restrict__ vh, const __nv_bfloat16* __restrict__ vl,
    __nv_bfloat16* __restrict__ ohp, __nv_bfloat16* __restrict__ olp)
{
    const uint32_t sb = smem_u32(smem_dyn);
    const int tid  = threadIdx.x;
    const int lane = tid & 31;
    const int wid  = tid >> 5;
    const int qt   = blockIdx.x;
    const int head = blockIdx.y;
    const int q0   = qt * 128;
    const int hoff = head * HD;
    const int wrow = wid * 16;

    const int arow = (lane & 7) + ((lane >> 3) & 1) * 8;
    const int acol = (lane >> 4) * 8;
    const int brow = (lane & 7) + (lane >> 4) * 8;
    const int bcol = ((lane >> 3) & 1) * 8;

    // Stage Q (hi/lo) into smem -- group 0
    for (int i = tid; i < 128 * 16; i += 256) {
        int row = i >> 4, ch = i & 15;
        size_t goff = (size_t)(q0 + row) * DIMN + hoff + ch * 8;
        uint32_t soff = (uint32_t)(row * FP2 + ch * 8) * 2;
        cp16(sb + FQH_B + soff, qh + goff);
        cp16(sb + FQL_B + soff, ql + goff);
    }
    CP_COMMIT();

    auto load_kv = [&](int stage, int kt) {
        const int k0 = kt * 64;
        const uint32_t stb = sb + FSTG_B + stage * FSTG_SZ;
        for (int i = tid; i < 64 * 16; i += 256) {
            int row = i >> 4, ch = i & 15;
            size_t goff = (size_t)(k0 + row) * DIMN + hoff + ch * 8;
            uint32_t soff = (uint32_t)(row * FP2 + ch * 8) * 2;
            cp16(stb + FKH_B + soff, kh + goff);
            cp16(stb + FKL_B + soff, kl + goff);
            cp16(stb + FVH_B + soff, vh + goff);
            cp16(stb + FVL_B + soff, vl + goff);
        }
    };

    int ktb, kte;
    if (qt < 24) { ktb = 0; kte = 56; }
    else { int j = (qt - 24) >> 1; ktb = 48 + j * 4; kte = ktb + 4; }
    const int nkt = kte - ktb;

    load_kv(0, ktb);      // group 1
    CP_COMMIT();

    // Q fragments -> registers (once). Wait group 0 (Q) done; KV0 may be in flight.
    uint32_t fq[8][4], fql[8][4];
    CP_WAIT(1);
    __syncthreads();
#pragma unroll
    for (int kc = 0; kc < 8; kc++) {
        uint32_t aoff = (uint32_t)((wrow + arow) * FP2 + kc * 16 + acol) * 2;
        ldm_x4(fq[kc],  sb + FQH_B + aoff);
        ldm_x4(fql[kc], sb + FQL_B + aoff);
    }

    float o[16][4];
#pragma unroll
    for (int i = 0; i < 16; i++)
#pragma unroll
        for (int j = 0; j < 4; j++) o[i][j] = 0.f;
    float mrun0 = -1e30f, mrun1 = -1e30f;
    float lrun0 = 0.f, lrun1 = 0.f;

    for (int i = 0; i < nkt; i++) {
        if (i + 1 < nkt) { load_kv((i + 1) & 1, ktb + i + 1); CP_COMMIT(); CP_WAIT(1); }
        else             { CP_WAIT(0); }
        __syncthreads();
        const uint32_t stb = sb + FSTG_B + (i & 1) * FSTG_SZ;

        float s[8][4];
#pragma unroll
        for (int nf = 0; nf < 8; nf++)
#pragma unroll
            for (int c = 0; c < 4; c++) s[nf][c] = 0.f;

#pragma unroll
        for (int kc = 0; kc < 8; kc++) {
            uint32_t fkh_[4][4], fkl_[4][4];
#pragma unroll
            for (int b = 0; b < 4; b++) {
                uint32_t boff = (uint32_t)((b * 16 + brow) * FP2 + kc * 16 + bcol) * 2;
                ldm_x4(fkh_[b], stb + FKH_B + boff);
                ldm_x4(fkl_[b], stb + FKL_B + boff);
            }
#pragma unroll
            for (int nf = 0; nf < 8; nf++) {
                uint32_t bh0 = fkh_[nf >> 1][(nf & 1) * 2], bh1 = fkh_[nf >> 1][(nf & 1) * 2 + 1];
                uint32_t bl0 = fkl_[nf >> 1][(nf & 1) * 2], bl1 = fkl_[nf >> 1][(nf & 1) * 2 + 1];
                mma_bf16(s[nf], fq[kc],  bh0, bh1);
                mma_bf16(s[nf], fq[kc],  bl0, bl1);
                mma_bf16(s[nf], fql[kc], bh0, bh1);
            }
        }

        float mx0 = -1e30f, mx1 = -1e30f;
#pragma unroll
        for (int nf = 0; nf < 8; nf++) {
            mx0 = fmaxf(mx0, fmaxf(s[nf][0], s[nf][1]));
            mx1 = fmaxf(mx1, fmaxf(s[nf][2], s[nf][3]));
        }
        mx0 = fmaxf(mx0, __shfl_xor_sync(0xffffffffu, mx0, 1));
        mx0 = fmaxf(mx0, __shfl_xor_sync(0xffffffffu, mx0, 2));
        mx1 = fmaxf(mx1, __shfl_xor_sync(0xffffffffu, mx1, 1));
        mx1 = fmaxf(mx1, __shfl_xor_sync(0xffffffffu, mx1, 2));
        float m0 = fmaxf(mrun0, mx0), m1 = fmaxf(mrun1, mx1);
        float a0 = exp2f(mrun0 - m0), a1 = exp2f(mrun1 - m1);
        mrun0 = m0; mrun1 = m1;

        float sum0 = 0.f, sum1 = 0.f;
#pragma unroll
        for (int nf = 0; nf < 8; nf++) {
            s[nf][0] = exp2f(s[nf][0] - m0);
            s[nf][1] = exp2f(s[nf][1] - m0);
            s[nf][2] = exp2f(s[nf][2] - m1);
            s[nf][3] = exp2f(s[nf][3] - m1);
            sum0 += s[nf][0] + s[nf][1];
            sum1 += s[nf][2] + s[nf][3];
        }
        sum0 += __shfl_xor_sync(0xffffffffu, sum0, 1);
        sum0 += __shfl_xor_sync(0xffffffffu, sum0, 2);
        sum1 += __shfl_xor_sync(0xffffffffu, sum1, 1);
        sum1 += __shfl_xor_sync(0xffffffffu, sum1, 2);
        lrun0 = lrun0 * a0 + sum0;
        lrun1 = lrun1 * a1 + sum1;

#pragma unroll
        for (int nf = 0; nf < 16; nf++) {
            o[nf][0] *= a0; o[nf][1] *= a0;
            o[nf][2] *= a1; o[nf][3] *= a1;
        }

        uint32_t pha[4][4], pla[4][4];
#pragma unroll
        for (int c2 = 0; c2 < 4; c2++) {
            splitpack(s[2 * c2][0],     s[2 * c2][1],     pha[c2][0], pla[c2][0]);
            splitpack(s[2 * c2][2],     s[2 * c2][3],     pha[c2][1], pla[c2][1]);
            splitpack(s[2 * c2 + 1][0], s[2 * c2 + 1][1], pha[c2][2], pla[c2][2]);
            splitpack(s[2 * c2 + 1][2], s[2 * c2 + 1][3], pha[c2][3], pla[c2][3]);
        }

#pragma unroll
        for (int c2 = 0; c2 < 4; c2++) {
#pragma unroll
            for (int db = 0; db < 8; db++) {
                uint32_t fvh_[4], fvl_[4];
                uint32_t voff = (uint32_t)((c2 * 16 + arow) * FP2 + db * 16 + acol) * 2;
                ldm_x4_t(fvh_, stb + FVH_B + voff);
                ldm_x4_t(fvl_, stb + FVL_B + voff);
                mma_bf16(o[2 * db],     pha[c2], fvh_[0], fvh_[1]);
                mma_bf16(o[2 * db + 1], pha[c2], fvh_[2], fvh_[3]);
                mma_bf16(o[2 * db],     pha[c2], fvl_[0], fvl_[1]);
                mma_bf16(o[2 * db + 1], pha[c2], fvl_[2], fvl_[3]);
                mma_bf16(o[2 * db],     pla[c2], fvh_[0], fvh_[1]);
                mma_bf16(o[2 * db + 1], pla[c2], fvh_[2], fvh_[3]);
            }
        }
        __syncthreads();
    }

    float inv0 = 1.0f / lrun0, inv1 = 1.0f / lrun1;
    int r0 = q0 + wrow + (lane >> 2);
    int r1 = r0 + 8;
    int cbase = hoff + (lane & 3) * 2;
#pragma unroll
    for (int nf = 0; nf < 16; nf++) {
        int col = cbase + nf * 8;
        float f0 = o[nf][0] * inv0, f1 = o[nf][1] * inv0;
        float f2 = o[nf][2] * inv1, f3 = o[nf][3] * inv1;
        uint32_t h01, l01, h23, l23;
        splitpack(f0, f1, h01, l01);
        splitpack(f2, f3, h23, l23);
        *(uint32_t*)&ohp[(size_t)r0 * DIMN + col] = h01;
        *(uint32_t*)&olp[(size_t)r0 * DIMN + col] = l01;
        *(uint32_t*)&ohp[(size_t)r1 * DIMN + col] = h23;
        *(uint32_t*)&olp[(size_t)r1 * DIMN + col] = l23;
    }
}

// ---------------------------------------------------------------------------
// Launch
// ---------------------------------------------------------------------------
extern "C" void kernel_launch(void* const* d_in, const int* in_sizes, int n_in,
                              void* d_out, int out_size)
{
    (void)in_sizes; (void)n_in; (void)out_size;
    const float* x     = (const float*)d_in[0];
    const float* Wq    = (const float*)d_in[1];
    const float* bq    = (const float*)d_in[2];
    const float* Wk    = (const float*)d_in[3];
    const float* bk    = (const float*)d_in[4];
    const float* Wv    = (const float*)d_in[5];
    const float* bv    = (const float*)d_in[6];
    const float* Wo    = (const float*)d_in[7];
    const float* bo    = (const float*)d_in[8];
    const float* gq    = (const float*)d_in[9];
    const float* gk    = (const float*)d_in[10];
    const float* freqs = (const float*)d_in[11];
    float* out = (float*)d_out;

    float *pq, *pk;
    cudaGetSymbolAddress((void**)&pq, g_q);
    cudaGetSymbolAddress((void**)&pk, g_k);

    __nv_bfloat16 *xh, *xl, *oh, *ol;
    __nv_bfloat16 *qh, *ql, *kh, *kl, *vh, *vl;
    __nv_bfloat16 *wqh, *wql, *wkh, *wkl, *wvh, *wvl, *woh, *wol;
    cudaGetSymbolAddress((void**)&xh, g_xh);   cudaGetSymbolAddress((void**)&xl, g_xl);
    cudaGetSymbolAddress((void**)&oh, g_oh);   cudaGetSymbolAddress((void**)&ol, g_ol);
    cudaGetSymbolAddress((void**)&qh, g_qh);   cudaGetSymbolAddress((void**)&ql, g_ql);
    cudaGetSymbolAddress((void**)&kh, g_kh);   cudaGetSymbolAddress((void**)&kl, g_kl);
    cudaGetSymbolAddress((void**)&vh, g_vh);   cudaGetSymbolAddress((void**)&vl, g_vl);
    cudaGetSymbolAddress((void**)&wqh, g_wqh); cudaGetSymbolAddress((void**)&wql, g_wql);
    cudaGetSymbolAddress((void**)&wkh, g_wkh); cudaGetSymbolAddress((void**)&wkl, g_wkl);
    cudaGetSymbolAddress((void**)&wvh, g_wvh); cudaGetSymbolAddress((void**)&wvl, g_wvl);
    cudaGetSymbolAddress((void**)&woh, g_woh); cudaGetSymbolAddress((void**)&wol, g_wol);

    cudaFuncSetAttribute(gemm_qkv, cudaFuncAttributeMaxDynamicSharedMemorySize,
                         GEMM_SMEM_BYTES);
    cudaFuncSetAttribute(gemm_out, cudaFuncAttributeMaxDynamicSharedMemorySize,
                         GEMM_SMEM_BYTES);
    cudaFuncSetAttribute(flash_hmma, cudaFuncAttributeMaxDynamicSharedMemorySize,
                         FLASH3_SMEM);

    const int nx = SEQ * DIMN, nw = DIMN * DIMN;
    cvt_hilo5<<<dim3(nx / 1024, 5), 256>>>(
        x, xh, xl, nx,
        Wq, wqh, wql, Wk, wkh, wkl, Wv, wvh, wvl, Wo, woh, wol, nw);

    dim3 qkvgrid(DIMN / 128, SEQ / 128, 3);   // (16, 28, 3)
    gemm_qkv<<<qkvgrid, 256, GEMM_SMEM_BYTES>>>(
        xh, xl, wqh, wql, wkh, wkl, wvh, wvl, bq, bk, bv, pq, pk, vh, vl);

    rms_rope<<<dim3(SEQ, 2), 256>>>(pq, pk, qh, ql, kh, kl, gq, gk, freqs);

    flash_hmma<<<dim3(SEQ / 128, NHEAD), 256, FLASH3_SMEM>>>(
        qh, ql, kh, kl, vh, vl, oh, ol);

    dim3 ogrid(DIMN / 128, SEQ / 128);        // (16, 28)
    gemm_out<<<ogrid, 256, GEMM_SMEM_BYTES>>>(oh, ol, woh, wol, bo, out);
}